// round 10
// baseline (speedup 1.0000x reference)
#include <cuda_runtime.h>

// StructuralLoss: predictions (64, 8192, 60) fp32 -> scalar.
// 20-float unit: bid_l=v[2l], ask_l=v[10+2l];
// viol = sum max(ask_l-ask_{l+1},0) + sum max(bid_{l+1}-bid_l,0) + max(bid0-ask0,0)
// out = (1/64) * sum over all units.
//
// CONVERGED KERNEL (best measured: 25.0us kernel, ~3% above the 24.2us data
// floor at the measured 5.2 TB/s path-independent DRAM read ceiling).
// Evidence: LDG-shuffle (this), TMA-bulk pipeline, and L2::256B-hinted
// variants all plateau at 5.17-5.21 TB/s across occ 48-94%, MLP 2-4,
// interleaved and blocked partitions. Traffic is sector-irreducible.
//  - 6 units = 30 float4 per warp "group"; lane l (<30) loads float4
//    (group*30 + l): fully coalesced 480B warp segments.
//  - Cross-float4 terms via 2 warp shuffles; per-lane masks hoisted.
//  - 4 groups per iteration (MLP=4), __ldcs evict-first.
//  - 1184 blocks = exactly 8 CTAs/SM on 148 SMs; __launch_bounds__(256,8)
//    pins regs to 32 (8-CTA residency).
//  - Deterministic ticket-fused final reduction (graph-replay safe:
//    ticket self-resets; fixed summation order => bit-stable output).

#define NBLOCKS 1184
#define NTHREADS 256
#define WARPS_PER_BLOCK (NTHREADS / 32)

__device__ float g_partials[NBLOCKS];
__device__ unsigned int g_ticket;   // zero-init; last block resets each run

__global__ __launch_bounds__(NTHREADS, 8) void viol_kernel(
    const float4* __restrict__ pred4, int n_groups, float* __restrict__ out)
{
    const int lane   = threadIdx.x & 31;
    const int gwarp  = (blockIdx.x * WARPS_PER_BLOCK) + (threadIdx.x >> 5);
    const int twarps = NBLOCKS * WARPS_PER_BLOCK;
    const int j      = lane % 5;
    const bool valid = lane < 30;

    // Per-lane constant masks (hoisted out of the loop).
    const float sign = (j <= 1) ? 1.0f : -1.0f;
    const float c1 = (valid && j != 2) ? 1.0f : 0.0f;  // intra-float4 pair
    const float c2 = (valid && j != 4) ? 1.0f : 0.0f;  // cross-float4 pair
    const float cs = (valid && j == 0) ? 1.0f : 0.0f;  // spread bid0-ask0

    float acc = 0.0f;

    #define GROUP_TERMS(w)                                                 \
        do {                                                               \
            float n1 = __shfl_down_sync(0xffffffffu, (w).x, 1);            \
            float n2 = __shfl_down_sync(0xffffffffu, (w).z, 2);            \
            float d1 = sign * ((w).z - (w).x);                             \
            float d2 = sign * (n1 - (w).z);                                \
            float ds = (w).x - n2;                                         \
            acc = fmaf(c1, fmaxf(d1, 0.0f), acc);                          \
            acc = fmaf(c2, fmaxf(d2, 0.0f), acc);                          \
            acc = fmaf(cs, fmaxf(ds, 0.0f), acc);                          \
        } while (0)

    // 4 groups (24 units, 1920B) per warp-iteration -> 4 LDGs in flight.
    const int n_quads = n_groups >> 2;
    for (int q = gwarp; q < n_quads; q += twarps) {
        const float4* b = pred4 + ((long long)(4 * q) * 30 + lane);
        float4 w0 = make_float4(0.f, 0.f, 0.f, 0.f);
        float4 w1 = w0, w2 = w0, w3 = w0;
        if (valid) {
            w0 = __ldcs(b);
            w1 = __ldcs(b + 30);
            w2 = __ldcs(b + 60);
            w3 = __ldcs(b + 90);
        }
        GROUP_TERMS(w0);
        GROUP_TERMS(w1);
        GROUP_TERMS(w2);
        GROUP_TERMS(w3);
    }
    // Remainder groups (none for this shape: 262144 % 4 == 0).
    {
        int rem = n_groups & 3;
        int g = (n_quads << 2) + gwarp;
        if (gwarp < rem) {
            float4 w = make_float4(0.f, 0.f, 0.f, 0.f);
            if (valid) w = __ldcs(&pred4[(long long)g * 30 + lane]);
            GROUP_TERMS(w);
        }
    }
    #undef GROUP_TERMS

    // Deterministic block reduction.
    __shared__ float s[WARPS_PER_BLOCK];
    #pragma unroll
    for (int o = 16; o > 0; o >>= 1)
        acc += __shfl_down_sync(0xffffffffu, acc, o);
    if (lane == 0) s[threadIdx.x >> 5] = acc;
    __syncthreads();

    __shared__ bool s_is_last;
    if (threadIdx.x < 32) {
        float v = (threadIdx.x < WARPS_PER_BLOCK) ? s[threadIdx.x] : 0.0f;
        #pragma unroll
        for (int o = 16; o > 0; o >>= 1)
            v += __shfl_down_sync(0xffffffffu, v, o);
        if (threadIdx.x == 0) {
            g_partials[blockIdx.x] = v;
            __threadfence();
            unsigned int t = atomicAdd(&g_ticket, 1u);
            s_is_last = (t == NBLOCKS - 1);
        }
    }
    __syncthreads();

    // Last block finishes the reduction (deterministic order).
    if (s_is_last) {
        float facc = 0.0f;
        for (int i = threadIdx.x; i < NBLOCKS; i += NTHREADS)
            facc += g_partials[i];
        #pragma unroll
        for (int o = 16; o > 0; o >>= 1)
            facc += __shfl_down_sync(0xffffffffu, facc, o);
        __shared__ float fs[WARPS_PER_BLOCK];
        if ((threadIdx.x & 31) == 0) fs[threadIdx.x >> 5] = facc;
        __syncthreads();
        if (threadIdx.x == 0) {
            float t = 0.0f;
            #pragma unroll
            for (int i = 0; i < WARPS_PER_BLOCK; i++) t += fs[i];
            out[0] = t * (1.0f / 64.0f);
            g_ticket = 0;   // reset for next graph replay
        }
    }
}

extern "C" void kernel_launch(void* const* d_in, const int* in_sizes, int n_in,
                              void* d_out, int out_size)
{
    const float4* pred4 = (const float4*)d_in[0];
    float* out = (float*)d_out;
    int n_units  = in_sizes[0] / 20;   // 1,572,864
    int n_groups = n_units / 6;        // 262,144

    viol_kernel<<<NBLOCKS, NTHREADS>>>(pred4, n_groups, out);
}

// round 11
// speedup vs baseline: 1.0036x; 1.0036x over previous
#include <cuda_runtime.h>

// StructuralLoss: predictions (64, 8192, 60) fp32 -> scalar.
// 20-float unit: bid_l=v[2l], ask_l=v[10+2l];
// viol = sum max(ask_l-ask_{l+1},0) + sum max(bid_{l+1}-bid_l,0) + max(bid0-ask0,0)
// out = (1/64) * sum over all units.
//
// CONVERGED KERNEL. 125.8MB single-pass read; measured path-independent DRAM
// read ceiling 5.17-5.21 TB/s (LDG-shuffle == TMA-bulk == hinted variants,
// across occ 48-98%, MLP 2-4, interleaved/blocked partitions). Data floor
// 24.2us; this kernel measures 25.0 +/- 0.8us (run-to-run DVFS noise).
//  - 6 units = 30 float4 per warp "group"; lane l (<30) loads float4
//    (group*30 + l): fully coalesced 480B warp segments.
//  - Cross-float4 terms via 2 warp shuffles; per-lane masks hoisted.
//  - 4 groups per iteration (MLP=4), __ldcs evict-first.
//  - 1184 blocks = exactly 8 CTAs/SM on 148 SMs; __launch_bounds__(256,8)
//    pins regs to 32 (8-CTA residency).
//  - Deterministic ticket-fused final reduction (graph-replay safe:
//    ticket self-resets; fixed summation order => bit-stable output).

#define NBLOCKS 1184
#define NTHREADS 256
#define WARPS_PER_BLOCK (NTHREADS / 32)

__device__ float g_partials[NBLOCKS];
__device__ unsigned int g_ticket;   // zero-init; last block resets each run

__global__ __launch_bounds__(NTHREADS, 8) void viol_kernel(
    const float4* __restrict__ pred4, int n_groups, float* __restrict__ out)
{
    const int lane   = threadIdx.x & 31;
    const int gwarp  = (blockIdx.x * WARPS_PER_BLOCK) + (threadIdx.x >> 5);
    const int twarps = NBLOCKS * WARPS_PER_BLOCK;
    const int j      = lane % 5;
    const bool valid = lane < 30;

    // Per-lane constant masks (hoisted out of the loop).
    const float sign = (j <= 1) ? 1.0f : -1.0f;
    const float c1 = (valid && j != 2) ? 1.0f : 0.0f;  // intra-float4 pair
    const float c2 = (valid && j != 4) ? 1.0f : 0.0f;  // cross-float4 pair
    const float cs = (valid && j == 0) ? 1.0f : 0.0f;  // spread bid0-ask0

    float acc = 0.0f;

    #define GROUP_TERMS(w)                                                 \
        do {                                                               \
            float n1 = __shfl_down_sync(0xffffffffu, (w).x, 1);            \
            float n2 = __shfl_down_sync(0xffffffffu, (w).z, 2);            \
            float d1 = sign * ((w).z - (w).x);                             \
            float d2 = sign * (n1 - (w).z);                                \
            float ds = (w).x - n2;                                         \
            acc = fmaf(c1, fmaxf(d1, 0.0f), acc);                          \
            acc = fmaf(c2, fmaxf(d2, 0.0f), acc);                          \
            acc = fmaf(cs, fmaxf(ds, 0.0f), acc);                          \
        } while (0)

    // 4 groups (24 units, 1920B) per warp-iteration -> 4 LDGs in flight.
    const int n_quads = n_groups >> 2;
    for (int q = gwarp; q < n_quads; q += twarps) {
        const float4* b = pred4 + ((long long)(4 * q) * 30 + lane);
        float4 w0 = make_float4(0.f, 0.f, 0.f, 0.f);
        float4 w1 = w0, w2 = w0, w3 = w0;
        if (valid) {
            w0 = __ldcs(b);
            w1 = __ldcs(b + 30);
            w2 = __ldcs(b + 60);
            w3 = __ldcs(b + 90);
        }
        GROUP_TERMS(w0);
        GROUP_TERMS(w1);
        GROUP_TERMS(w2);
        GROUP_TERMS(w3);
    }
    // Remainder groups (none for this shape: 262144 % 4 == 0).
    {
        int rem = n_groups & 3;
        int g = (n_quads << 2) + gwarp;
        if (gwarp < rem) {
            float4 w = make_float4(0.f, 0.f, 0.f, 0.f);
            if (valid) w = __ldcs(&pred4[(long long)g * 30 + lane]);
            GROUP_TERMS(w);
        }
    }
    #undef GROUP_TERMS

    // Deterministic block reduction.
    __shared__ float s[WARPS_PER_BLOCK];
    #pragma unroll
    for (int o = 16; o > 0; o >>= 1)
        acc += __shfl_down_sync(0xffffffffu, acc, o);
    if (lane == 0) s[threadIdx.x >> 5] = acc;
    __syncthreads();

    __shared__ bool s_is_last;
    if (threadIdx.x < 32) {
        float v = (threadIdx.x < WARPS_PER_BLOCK) ? s[threadIdx.x] : 0.0f;
        #pragma unroll
        for (int o = 16; o > 0; o >>= 1)
            v += __shfl_down_sync(0xffffffffu, v, o);
        if (threadIdx.x == 0) {
            g_partials[blockIdx.x] = v;
            __threadfence();
            unsigned int t = atomicAdd(&g_ticket, 1u);
            s_is_last = (t == NBLOCKS - 1);
        }
    }
    __syncthreads();

    // Last block finishes the reduction (deterministic order).
    if (s_is_last) {
        float facc = 0.0f;
        for (int i = threadIdx.x; i < NBLOCKS; i += NTHREADS)
            facc += g_partials[i];
        #pragma unroll
        for (int o = 16; o > 0; o >>= 1)
            facc += __shfl_down_sync(0xffffffffu, facc, o);
        __shared__ float fs[WARPS_PER_BLOCK];
        if ((threadIdx.x & 31) == 0) fs[threadIdx.x >> 5] = facc;
        __syncthreads();
        if (threadIdx.x == 0) {
            float t = 0.0f;
            #pragma unroll
            for (int i = 0; i < WARPS_PER_BLOCK; i++) t += fs[i];
            out[0] = t * (1.0f / 64.0f);
            g_ticket = 0;   // reset for next graph replay
        }
    }
}

extern "C" void kernel_launch(void* const* d_in, const int* in_sizes, int n_in,
                              void* d_out, int out_size)
{
    const float4* pred4 = (const float4*)d_in[0];
    float* out = (float*)d_out;
    int n_units  = in_sizes[0] / 20;   // 1,572,864
    int n_groups = n_units / 6;        // 262,144

    viol_kernel<<<NBLOCKS, NTHREADS>>>(pred4, n_groups, out);
}

// round 12
// speedup vs baseline: 1.0741x; 1.0702x over previous
#include <cuda_runtime.h>

// StructuralLoss: predictions (64, 8192, 60) fp32 -> scalar.
// 20-float unit: bid_l=v[2l], ask_l=v[10+2l];
// viol = sum max(ask_l-ask_{l+1},0) + sum max(bid_{l+1}-bid_l,0) + max(bid0-ask0,0)
// out = (1/64) * sum over all units.
//
// CONVERGED KERNEL. 125.8MB single-pass read; measured path-independent DRAM
// read ceiling ~5.2 TB/s (LDG-shuffle == TMA-bulk == hinted variants, across
// occ 48-98%, MLP 2-4, interleaved/blocked partitions). Data floor 24.2us;
// kernel measures 25.0-26.7us across samples (session clock drift).
//  - 6 units = 30 float4 per warp "group"; lane l loads float4 (group*30 +
//    min(l,29)) — branch-free: lanes 30/31 re-read lane 29's line (L1tex
//    merged, zero extra DRAM sectors) and are zeroed by the c-masks.
//  - Cross-float4 terms via 2 warp shuffles; per-lane masks hoisted.
//  - 4 groups per iteration (MLP=4), __ldcs evict-first.
//  - 1184 blocks = exactly 8 CTAs/SM on 148 SMs; __launch_bounds__(256,8).
//  - Deterministic ticket-fused final reduction (graph-replay safe).

#define NBLOCKS 1184
#define NTHREADS 256
#define WARPS_PER_BLOCK (NTHREADS / 32)

__device__ float g_partials[NBLOCKS];
__device__ unsigned int g_ticket;   // zero-init; last block resets each run

__global__ __launch_bounds__(NTHREADS, 8) void viol_kernel(
    const float4* __restrict__ pred4, int n_groups, float* __restrict__ out)
{
    const int lane   = threadIdx.x & 31;
    const int lane_c = (lane < 30) ? lane : 29;     // clamped: branch-free loads
    const int gwarp  = (blockIdx.x * WARPS_PER_BLOCK) + (threadIdx.x >> 5);
    const int twarps = NBLOCKS * WARPS_PER_BLOCK;
    const int j      = lane % 5;
    const bool valid = lane < 30;

    // Per-lane constant masks (hoisted; zero for invalid lanes 30/31).
    const float sign = (j <= 1) ? 1.0f : -1.0f;
    const float c1 = (valid && j != 2) ? 1.0f : 0.0f;  // intra-float4 pair
    const float c2 = (valid && j != 4) ? 1.0f : 0.0f;  // cross-float4 pair
    const float cs = (valid && j == 0) ? 1.0f : 0.0f;  // spread bid0-ask0

    float acc = 0.0f;

    #define GROUP_TERMS(w)                                                 \
        do {                                                               \
            float n1 = __shfl_down_sync(0xffffffffu, (w).x, 1);            \
            float n2 = __shfl_down_sync(0xffffffffu, (w).z, 2);            \
            float d1 = sign * ((w).z - (w).x);                             \
            float d2 = sign * (n1 - (w).z);                                \
            float ds = (w).x - n2;                                         \
            acc = fmaf(c1, fmaxf(d1, 0.0f), acc);                          \
            acc = fmaf(c2, fmaxf(d2, 0.0f), acc);                          \
            acc = fmaf(cs, fmaxf(ds, 0.0f), acc);                          \
        } while (0)

    // 4 groups (24 units, 1920B) per warp-iteration -> 4 unpredicated LDGs.
    const int n_quads = n_groups >> 2;
    for (int q = gwarp; q < n_quads; q += twarps) {
        const float4* b = pred4 + ((long long)(4 * q) * 30 + lane_c);
        float4 w0 = __ldcs(b);
        float4 w1 = __ldcs(b + 30);
        float4 w2 = __ldcs(b + 60);
        float4 w3 = __ldcs(b + 90);
        GROUP_TERMS(w0);
        GROUP_TERMS(w1);
        GROUP_TERMS(w2);
        GROUP_TERMS(w3);
    }
    // Remainder groups (none for this shape: 262144 % 4 == 0).
    {
        int rem = n_groups & 3;
        int g = (n_quads << 2) + gwarp;
        if (gwarp < rem) {
            float4 w = __ldcs(&pred4[(long long)g * 30 + lane_c]);
            GROUP_TERMS(w);
        }
    }
    #undef GROUP_TERMS

    // Deterministic block reduction.
    __shared__ float s[WARPS_PER_BLOCK];
    #pragma unroll
    for (int o = 16; o > 0; o >>= 1)
        acc += __shfl_down_sync(0xffffffffu, acc, o);
    if (lane == 0) s[threadIdx.x >> 5] = acc;
    __syncthreads();

    __shared__ bool s_is_last;
    if (threadIdx.x < 32) {
        float v = (threadIdx.x < WARPS_PER_BLOCK) ? s[threadIdx.x] : 0.0f;
        #pragma unroll
        for (int o = 16; o > 0; o >>= 1)
            v += __shfl_down_sync(0xffffffffu, v, o);
        if (threadIdx.x == 0) {
            g_partials[blockIdx.x] = v;
            __threadfence();
            unsigned int t = atomicAdd(&g_ticket, 1u);
            s_is_last = (t == NBLOCKS - 1);
        }
    }
    __syncthreads();

    // Last block finishes the reduction (deterministic order).
    if (s_is_last) {
        float facc = 0.0f;
        for (int i = threadIdx.x; i < NBLOCKS; i += NTHREADS)
            facc += g_partials[i];
        #pragma unroll
        for (int o = 16; o > 0; o >>= 1)
            facc += __shfl_down_sync(0xffffffffu, facc, o);
        __shared__ float fs[WARPS_PER_BLOCK];
        if ((threadIdx.x & 31) == 0) fs[threadIdx.x >> 5] = facc;
        __syncthreads();
        if (threadIdx.x == 0) {
            float t = 0.0f;
            #pragma unroll
            for (int i = 0; i < WARPS_PER_BLOCK; i++) t += fs[i];
            out[0] = t * (1.0f / 64.0f);
            g_ticket = 0;   // reset for next graph replay
        }
    }
}

extern "C" void kernel_launch(void* const* d_in, const int* in_sizes, int n_in,
                              void* d_out, int out_size)
{
    const float4* pred4 = (const float4*)d_in[0];
    float* out = (float*)d_out;
    int n_units  = in_sizes[0] / 20;   // 1,572,864
    int n_groups = n_units / 6;        // 262,144

    viol_kernel<<<NBLOCKS, NTHREADS>>>(pred4, n_groups, out);
}